// round 11
// baseline (speedup 1.0000x reference)
#include <cuda_runtime.h>
#include <cuda_bf16.h>
#include <cstddef>
#include <cstdint>

// Depthwise cross-correlation — R10: kx-paired fp32x2 FMA, 2 CTAs/SM,
// persistent grid + cp.async double buffering.
//   out[ch, oy, ox] = sum_{ky,kx} x[ch, oy+ky, ox+kx] * z[ch, ky, kx]
//   32768 channels, x: 31x31, z: 7x7, out: 25x25 (VALID, no flip)
//
// f32x2 lanes = (even-kx partial, odd-kx partial) of ONE output; folded with
// one FADD at store. kx padded 7->8 with a zero tap, so both FFMA2 operands
// are memory-adjacent pairs (no repacking) and window overrun is harmless.

#define NCHAN   32768
#define HX      31
#define HZ      7
#define HO      25
#define XSZ     961
#define ZSZ     49
#define OSZ     625
#define CPG     8               // channels per group: 8*961 floats = 16B-multiple
#define TPC     25              // threads per channel (one per output column)
#define THREADS 256
#define CTAS_PER_SM 2
#define GRID    (152 * CTAS_PER_SM)
#define NGROUPS (NCHAN / CPG)   // 4096 exactly, no tail

#define GX_FLOATS (CPG * XSZ)       // 7688
#define GX_PAD    (GX_FLOATS + 8)   // slack for the last channel's window overrun
#define GZ_FLOATS (CPG * ZSZ)       // 392
#define GX_V4     (GX_FLOATS / 4)   // 1922
#define GZ_V4     (GZ_FLOATS / 4)   // 98

__device__ __forceinline__ void ffma2(float2& d, const float2& a, const float2& b) {
    asm("fma.rn.f32x2 %0, %1, %2, %0;"
        : "+l"(reinterpret_cast<unsigned long long&>(d))
        : "l"(reinterpret_cast<const unsigned long long&>(a)),
          "l"(reinterpret_cast<const unsigned long long&>(b)));
}

__device__ __forceinline__ void cpasync16(uint32_t saddr, const void* gaddr) {
    asm volatile("cp.async.cg.shared.global [%0], [%1], 16;"
                 :: "r"(saddr), "l"(gaddr) : "memory");
}
#define CP_COMMIT() asm volatile("cp.async.commit_group;" ::: "memory")
#define CP_WAIT1()  asm volatile("cp.async.wait_group 1;" ::: "memory")
#define CP_WAIT0()  asm volatile("cp.async.wait_group 0;" ::: "memory")

__device__ __forceinline__ void prefetch_group(
    int g, float* xs, float* zs,
    const float* __restrict__ x, const float* __restrict__ z, int tid)
{
    const float4* gx = reinterpret_cast<const float4*>(x) + (size_t)g * GX_V4;
    const float4* gz = reinterpret_cast<const float4*>(z) + (size_t)g * GZ_V4;
    const uint32_t sx = (uint32_t)__cvta_generic_to_shared(xs);
    const uint32_t sz = (uint32_t)__cvta_generic_to_shared(zs);
    #pragma unroll
    for (int j = tid; j < GX_V4; j += THREADS)      // 7-8 per thread
        cpasync16(sx + (uint32_t)j * 16u, gx + j);
    if (tid < GZ_V4)
        cpasync16(sz + (uint32_t)tid * 16u, gz + tid);
}

__device__ __forceinline__ void compute_group(
    int g, const float* __restrict__ xs, const float* __restrict__ zs,
    float* __restrict__ out, int lch, int tx)
{
    if (lch >= CPG) return;                  // copy-only lanes; no syncs inside

    const float* xc = xs + lch * XSZ;
    const float* zc = zs + lch * ZSZ;

    // Taps as kx pairs, kx padded to 8 with a zero column: 28 float2 (56 regs).
    float2 kt[HZ][4];
    #pragma unroll
    for (int ky = 0; ky < HZ; ++ky) {
        kt[ky][0] = make_float2(zc[7 * ky + 0], zc[7 * ky + 1]);
        kt[ky][1] = make_float2(zc[7 * ky + 2], zc[7 * ky + 3]);
        kt[ky][2] = make_float2(zc[7 * ky + 4], zc[7 * ky + 5]);
        kt[ky][3] = make_float2(zc[7 * ky + 6], 0.0f);
    }

    // Ring of 7 accumulator pairs (even/odd-kx partials of one output each).
    float2 acc[HZ];
    #pragma unroll
    for (int i = 0; i < HZ; ++i) acc[i] = make_float2(0.0f, 0.0f);

    const float* xb = xc + tx;
    float* go = out + (size_t)(g * CPG + lch) * OSZ + tx;

    #pragma unroll
    for (int r = 0; r < HX; ++r) {
        // 8-float window; w[7] only ever multiplies the zero tap.
        float w[8];
        #pragma unroll
        for (int c = 0; c < 8; ++c) w[c] = xb[r * HX + c];
        const float2 a0 = make_float2(w[0], w[1]);
        const float2 a1 = make_float2(w[2], w[3]);
        const float2 a2 = make_float2(w[4], w[5]);
        const float2 a3 = make_float2(w[6], w[7]);

        #pragma unroll
        for (int ky = 0; ky < HZ; ++ky) {
            const int oy = r - ky;
            if (oy >= 0 && oy < HO) {
                const int s = oy % HZ;        // compile-time after unroll
                ffma2(acc[s], a0, kt[ky][0]);
                ffma2(acc[s], a1, kt[ky][1]);
                ffma2(acc[s], a2, kt[ky][2]);
                ffma2(acc[s], a3, kt[ky][3]);
            }
        }

        if (r >= HZ - 1) {                    // output row r-6 complete
            const int oy = r - (HZ - 1);
            const int s  = oy % HZ;
            go[oy * HO] = acc[s].x + acc[s].y;   // fold even/odd-kx partials
            acc[s] = make_float2(0.0f, 0.0f);
        }
    }
}

__global__ __launch_bounds__(THREADS, CTAS_PER_SM)
void dwxcorr_kx2(const float* __restrict__ z,
                 const float* __restrict__ x,
                 float* __restrict__ out) {
    extern __shared__ float smem[];
    float* xb0 = smem;
    float* xb1 = smem + GX_PAD;
    float* zb0 = smem + 2 * GX_PAD;
    float* zb1 = zb0 + GZ_FLOATS;

    const int tid = threadIdx.x;
    const int lch = tid / TPC;        // local channel 0..7 (>=8: copy-only)
    const int tx  = tid - lch * TPC;  // output column 0..24

    int g = blockIdx.x;
    if (g < NGROUPS)
        prefetch_group(g, xb0, zb0, x, z, tid);
    CP_COMMIT();

    int i = 0;
    for (; g < NGROUPS; g += GRID, ++i) {
        float* xc = (i & 1) ? xb1 : xb0;
        float* zc = (i & 1) ? zb1 : zb0;
        float* xn = (i & 1) ? xb0 : xb1;
        float* zn = (i & 1) ? zb0 : zb1;

        const int gn = g + GRID;
        if (gn < NGROUPS) {
            prefetch_group(gn, xn, zn, x, z, tid);   // background fill
            CP_COMMIT();
            CP_WAIT1();                               // current group landed
        } else {
            CP_WAIT0();
        }
        __syncthreads();

        compute_group(g, xc, zc, out, lch, tx);

        __syncthreads();                              // done reading xc/zc
    }
}

extern "C" void kernel_launch(void* const* d_in, const int* in_sizes, int n_in,
                              void* d_out, int out_size) {
    // metadata order: d_in[0] = z_f [128,256,7,7], d_in[1] = x_f [128,256,31,31]
    const float* z = (const float*)d_in[0];
    const float* x = (const float*)d_in[1];
    float* out = (float*)d_out;

    const size_t smem = (size_t)(2 * GX_PAD + 2 * GZ_FLOATS) * sizeof(float); // 64704 B
    cudaFuncSetAttribute(dwxcorr_kx2,
                         cudaFuncAttributeMaxDynamicSharedMemorySize, (int)smem);
    dwxcorr_kx2<<<GRID, THREADS, smem>>>(z, x, out);
}

// round 12
// speedup vs baseline: 1.0971x; 1.0971x over previous
#include <cuda_runtime.h>
#include <cuda_bf16.h>
#include <cstddef>
#include <cstdint>

// Depthwise cross-correlation — R12: output-column-paired fp32x2 FMA.
//   out[ch, oy, ox] = sum_{ky,kx} x[ch, oy+ky, ox+kx] * z[ch, ky, kx]
//   32768 channels, x: 31x31, z: 7x7, out: 25x25 (VALID, no flip)
//
// f32x2 lanes = outputs (oy, 2t) and (oy, 2t+1) of one channel. One 8-float
// window per row serves both outputs (LDS bytes/output halved vs R10), taps
// are (z,z) duplicated in regs, no fold-add, no zero-pad FMA waste.
// Warp = 2 channels (one per half-warp, lanes 0..12 active). Channel pitch
// 961 = 1 (mod 32) makes every LDS.32 wavefront conflict-free (half-warps
// use disjoint even/odd bank sets; lanes within a half-warp distinct banks).
// 3 CTAs/SM x 128 threads, persistent, cp.async double-buffered.

#define NCHAN   32768
#define HX      31
#define HZ      7
#define HO      25
#define XSZ     961
#define ZSZ     49
#define OSZ     625
#define CPG     8               // channels per group (2 per warp)
#define THREADS 128
#define CTAS_PER_SM 3
#define GRID    (152 * CTAS_PER_SM)   // 456
#define NGROUPS (NCHAN / CPG)         // 4096 exactly

#define GX_FLOATS (CPG * XSZ)         // 7688 (30752 B, 16B-multiple)
#define GX_PAD    (GX_FLOATS + 4)     // +4: lane-12 window overrun slack
#define GZ_FLOATS (CPG * ZSZ)         // 392 (1568 B, 16B-multiple)
#define GX_V4     (GX_FLOATS / 4)     // 1922
#define GZ_V4     (GZ_FLOATS / 4)     // 98

__device__ __forceinline__ void ffma2(float2& d, const float2& a, const float2& b) {
    asm("fma.rn.f32x2 %0, %1, %2, %0;"
        : "+l"(reinterpret_cast<unsigned long long&>(d))
        : "l"(reinterpret_cast<const unsigned long long&>(a)),
          "l"(reinterpret_cast<const unsigned long long&>(b)));
}

__device__ __forceinline__ void cpasync16(uint32_t saddr, const void* gaddr) {
    asm volatile("cp.async.cg.shared.global [%0], [%1], 16;"
                 :: "r"(saddr), "l"(gaddr) : "memory");
}
#define CP_COMMIT() asm volatile("cp.async.commit_group;" ::: "memory")
#define CP_WAIT1()  asm volatile("cp.async.wait_group 1;" ::: "memory")
#define CP_WAIT0()  asm volatile("cp.async.wait_group 0;" ::: "memory")

__device__ __forceinline__ void prefetch_group(
    int g, float* xs, float* zs,
    const float* __restrict__ x, const float* __restrict__ z, int tid)
{
    const float4* gx = reinterpret_cast<const float4*>(x) + (size_t)g * GX_V4;
    const float4* gz = reinterpret_cast<const float4*>(z) + (size_t)g * GZ_V4;
    const uint32_t sx = (uint32_t)__cvta_generic_to_shared(xs);
    const uint32_t sz = (uint32_t)__cvta_generic_to_shared(zs);
    #pragma unroll
    for (int j = tid; j < GX_V4; j += THREADS)     // ~15 per thread
        cpasync16(sx + (uint32_t)j * 16u, gx + j);
    if (tid < GZ_V4)
        cpasync16(sz + (uint32_t)tid * 16u, gz + tid);
}

__device__ __forceinline__ void compute_group(
    int g, const float* __restrict__ xs, const float* __restrict__ zs,
    float* __restrict__ out, int lch, int l, bool active, bool store_hi)
{
    if (!active) return;                 // lanes 13..15 of each half-warp idle

    const float* xc = xs + lch * XSZ;
    const float* zc = zs + lch * ZSZ;
    const int col0 = 2 * l;              // output columns (col0, col0+1)

    // Taps duplicated into both f32x2 lanes: 49 float2 (98 regs), broadcast LDS.
    float2 kt[ZSZ];
    #pragma unroll
    for (int j = 0; j < ZSZ; ++j) {
        const float zv = zc[j];
        kt[j] = make_float2(zv, zv);
    }

    // Ring of 7 accumulators; lanes = the two adjacent output columns.
    float2 acc[HZ];
    #pragma unroll
    for (int i = 0; i < HZ; ++i) acc[i] = make_float2(0.0f, 0.0f);

    const float* xb = xc + col0;
    float* go = out + (size_t)(g * CPG + lch) * OSZ + col0;

    #pragma unroll
    for (int r = 0; r < HX; ++r) {
        // 8-float window serves both output columns. Lane l=12 reads one float
        // past the row (next row / +4 pad) into w[7]; its .y result is dropped.
        float w[8];
        #pragma unroll
        for (int c = 0; c < 8; ++c) w[c] = xb[r * HX + c];

        const float2 p0 = make_float2(w[0], w[1]);   // even pairs: free
        const float2 p1 = make_float2(w[2], w[3]);
        const float2 p2 = make_float2(w[4], w[5]);
        const float2 p3 = make_float2(w[6], w[7]);
        const float2 q0 = make_float2(w[1], w[2]);   // odd pairs: MOV-built
        const float2 q1 = make_float2(w[3], w[4]);
        const float2 q2 = make_float2(w[5], w[6]);

        #pragma unroll
        for (int ky = 0; ky < HZ; ++ky) {
            const int oy = r - ky;
            if (oy >= 0 && oy < HO) {
                const int s = oy % HZ;               // const after unroll
                const float2* kz = &kt[ky * HZ];
                ffma2(acc[s], p0, kz[0]);            // kx=0: (x[c0],   x[c0+1])
                ffma2(acc[s], q0, kz[1]);            // kx=1: (x[c0+1], x[c0+2])
                ffma2(acc[s], p1, kz[2]);
                ffma2(acc[s], q1, kz[3]);
                ffma2(acc[s], p2, kz[4]);
                ffma2(acc[s], q2, kz[5]);
                ffma2(acc[s], p3, kz[6]);            // kx=6: (x[c0+6], x[c0+7])
            }
        }

        if (r >= HZ - 1) {                           // output row r-6 complete
            const int oy = r - (HZ - 1);
            const int s  = oy % HZ;
            go[oy * HO] = acc[s].x;
            if (store_hi) go[oy * HO + 1] = acc[s].y;
            acc[s] = make_float2(0.0f, 0.0f);
        }
    }
}

__global__ __launch_bounds__(THREADS, CTAS_PER_SM)
void dwxcorr_op2(const float* __restrict__ z,
                 const float* __restrict__ x,
                 float* __restrict__ out) {
    extern __shared__ float smem[];
    float* xb0 = smem;
    float* xb1 = smem + GX_PAD;
    float* zb0 = smem + 2 * GX_PAD;
    float* zb1 = zb0 + GZ_FLOATS;

    const int tid  = threadIdx.x;
    const int warp = tid >> 5;
    const int lane = tid & 31;
    const int h    = lane >> 4;          // half-warp: channel select
    const int l    = lane & 15;          // lane within half-warp
    const int lch  = 2 * warp + h;       // local channel 0..7
    const bool active   = (l <= 12);     // 13 column-pair slots cover 25 cols
    const bool store_hi = (l < 12);      // lane 12: column 24 only

    int g = blockIdx.x;
    if (g < NGROUPS)
        prefetch_group(g, xb0, zb0, x, z, tid);
    CP_COMMIT();

    int i = 0;
    for (; g < NGROUPS; g += GRID, ++i) {
        float* xc = (i & 1) ? xb1 : xb0;
        float* zc = (i & 1) ? zb1 : zb0;
        float* xn = (i & 1) ? xb0 : xb1;
        float* zn = (i & 1) ? zb0 : zb1;

        const int gn = g + GRID;
        if (gn < NGROUPS) {
            prefetch_group(gn, xn, zn, x, z, tid);   // background fill
            CP_COMMIT();
            CP_WAIT1();                               // current group landed
        } else {
            CP_WAIT0();
        }
        __syncthreads();

        compute_group(g, xc, zc, out, lch, l, active, store_hi);

        __syncthreads();                              // done reading xc/zc
    }
}

extern "C" void kernel_launch(void* const* d_in, const int* in_sizes, int n_in,
                              void* d_out, int out_size) {
    // metadata order: d_in[0] = z_f [128,256,7,7], d_in[1] = x_f [128,256,31,31]
    const float* z = (const float*)d_in[0];
    const float* x = (const float*)d_in[1];
    float* out = (float*)d_out;

    const size_t smem = (size_t)(2 * GX_PAD + 2 * GZ_FLOATS) * sizeof(float); // 64672 B
    cudaFuncSetAttribute(dwxcorr_op2,
                         cudaFuncAttributeMaxDynamicSharedMemorySize, (int)smem);
    dwxcorr_op2<<<GRID, THREADS, smem>>>(z, x, out);
}